// round 15
// baseline (speedup 1.0000x reference)
#include <cuda_runtime.h>
#include <cstdint>

// CIC deposition: 10M particles -> 256^3 float grid.
// Round 15: 8-lane-group cooperation — ONE RED instruction per particle.
// 2x2x2-block permuted scratch (block = 32B sector, quad = xbit half,
// quad lane = ybit*2+zbit). Lane (h,sz,sy) of each 8-lane group covers
// x-half h, z-block sz, y-block sy of the group's current particle, so all
// (up to) 8 target quads share one RED instruction -> maximal opportunity
// for intra-instruction sector/line merging at the LSU/LTS.
// Sectors/particle unchanged (3.375); R14 measured effective ~3.12 with
// z-adjacency in-instruction; this adds y and full-x grouping.

static constexpr float GMINF = -10.0f;
static constexpr float DXF   = (float)(20.0 / 255.0);

static constexpr size_t NBLK = 128u * 128u * 128u;       // 2,097,152 blocks
__device__ __align__(32) float g_scratch[NBLK * 8];      // 64MB

__global__ void zero_scratch_kernel(int n4) {
    int i = blockIdx.x * blockDim.x + threadIdx.x;
    if (i < n4) ((float4*)g_scratch)[i] = make_float4(0.f, 0.f, 0.f, 0.f);
}

__device__ __forceinline__ void red_v4p(float* p, float a, float b, float c, float d, int pred) {
    asm volatile(
        "{\n\t"
        ".reg .pred q;\n\t"
        "setp.ne.s32 q, %5, 0;\n\t"
        "@q red.global.add.v4.f32 [%0], {%1, %2, %3, %4};\n\t"
        "}"
        :: "l"(p), "f"(a), "f"(b), "f"(c), "f"(d), "r"(pred) : "memory");
}

__global__ void __launch_bounds__(256) cic_deposit_kernel(
    const float* __restrict__ pos,
    const float* __restrict__ wgt,
    int n)
{
    int i    = blockIdx.x * blockDim.x + threadIdx.x;   // one particle per thread
    int lane = threadIdx.x & 31;
    int h    = lane & 1;          // x-half this lane serves
    int sz   = (lane >> 1) & 1;   // z-block this lane serves
    int sy   = (lane >> 2) & 1;   // y-block this lane serves

    // ---- own particle -> derived values ----
    float xw0 = 0.f, xw1 = 0.f, oyv = 0.f, ozv = 0.f;
    int B = 0, fl = 0;   // fl: 1=valid | bx<<1 | by<<2 | bz<<3 | lx<<4 | ly<<5 | lz<<6

    if (i < n) {
        float px = __ldcs(pos + 3 * (size_t)i + 0);
        float py = __ldcs(pos + 3 * (size_t)i + 1);
        float pz = __ldcs(pos + 3 * (size_t)i + 2);
        float w  = __ldcs(wgt + i);

        // Match JAX float32 arithmetic: subtract then IEEE divide
        float fx = (px - GMINF) / DXF;
        float fy = (py - GMINF) / DXF;
        float fz = (pz - GMINF) / DXF;

        float ixf = floorf(fx), iyf = floorf(fy), izf = floorf(fz);
        int cx = (int)ixf, cy = (int)iyf, cz = (int)izf;

        if ((unsigned)cx <= 255u && (unsigned)cy <= 255u && (unsigned)cz <= 255u) {
            float ox = fx - ixf;
            oyv = fy - iyf;
            ozv = fz - izf;
            xw0 = w * (1.0f - ox);   // corner weight = ((w*X)*Y)*Z association
            xw1 = w * ox;
            B = ((cx >> 1) * 128 + (cy >> 1)) * 128 + (cz >> 1);
            fl = 1 | ((cx & 1) << 1) | ((cy & 1) << 2) | ((cz & 1) << 3)
                   | ((int)(cx < 255) << 4) | ((int)(cy < 255) << 5) | ((int)(cz < 255) << 6);
        }
    }

    // ---- 8 rounds: group (8g..8g+7) processes member r's particle ----
    #pragma unroll
    for (int r = 0; r < 8; r++) {
        const unsigned FULL = 0xffffffffu;
        float XW0 = __shfl_sync(FULL, xw0, r, 8);
        float XW1 = __shfl_sync(FULL, xw1, r, 8);
        float OY  = __shfl_sync(FULL, oyv, r, 8);
        float OZ  = __shfl_sync(FULL, ozv, r, 8);
        int   Bb  = __shfl_sync(FULL, B,   r, 8);
        int   F   = __shfl_sync(FULL, fl,  r, 8);

        int val = F & 1;
        int bx = (F >> 1) & 1, by = (F >> 2) & 1, bz = (F >> 3) & 1;
        int lx = (F >> 4) & 1, ly = (F >> 5) & 1, lz = (F >> 6) & 1;

        float wy0 = 1.0f - OY, wy1 = OY;
        float wz0 = 1.0f - OZ, wz1 = OZ;

        // z values for this lane's z-block (quad lane order: ybit*2 + zbit)
        float zv0 = sz ? wz1 : (bz ? 0.0f : wz0);
        float zv1 = sz ? 0.0f : (bz ? wz0 : wz1);
        // y values for this lane's y-block
        float yv0 = sy ? wy1 : (by ? 0.0f : wy0);
        float yv1 = sy ? 0.0f : (by ? wy0 : wy1);
        float xw  = h ? XW1 : XW0;

        // lane address: x-half h=0 -> xbit=bx in block X; h=1 -> bx ? block X+1 : +4
        int xoff = h ? (bx ? 131072 : 4) : (bx << 2);   // floats; 131072 = 128*128*8
        float* Q = g_scratch + ((size_t)(unsigned)Bb << 3)
                 + (size_t)(xoff + (sz << 3) + (sy << 10));

        int p = val
              & (h  ? (bx ? lx : 1) : 1)
              & (sz ? (bz & lz) : 1)
              & (sy ? (by & ly) : 1);

        red_v4p(Q, xw * (yv0 * zv0), xw * (yv0 * zv1),
                   xw * (yv1 * zv0), xw * (yv1 * zv1), p);
    }
}

// depermute (proven ~28us): thread t builds out float4 (4 z values) from fixed
// (xbit,ybit) float2 halves of two adjacent z-blocks.
__global__ void __launch_bounds__(256) depermute_kernel(float4* __restrict__ out, int n4) {
    int t = blockIdx.x * blockDim.x + threadIdx.x;
    if (t >= n4) return;
    int z4 = t & 63;          // z = 4*z4 .. 4*z4+3 -> z-blocks 2*z4, 2*z4+1
    int y  = (t >> 6) & 255;
    int x  = t >> 14;
    int X = x >> 1, Y = y >> 1;
    int off = ((x & 1) << 2) | ((y & 1) << 1);
    size_t bidx = (((size_t)X * 128 + (size_t)Y) * 128 + (size_t)(z4 << 1));
    const float* b0 = g_scratch + (bidx << 3) + off;
    float2 a = *(const float2*)b0;         // z-block 2z4:   z = 4z4, 4z4+1
    float2 b = *(const float2*)(b0 + 8);   // z-block 2z4+1: z = 4z4+2, 4z4+3
    out[t] = make_float4(a.x, a.y, b.x, b.y);
}

extern "C" void kernel_launch(void* const* d_in, const int* in_sizes, int n_in,
                              void* d_out, int out_size) {
    const float* positions = (const float*)d_in[0];
    const float* weights   = (const float*)d_in[1];
    float* grid = (float*)d_out;

    int n_particles = in_sizes[1];  // weights element count = N

    // 1) zero the 64MB permuted scratch
    int nz4 = (int)(NBLK * 8 / 4);
    zero_scratch_kernel<<<(nz4 + 255) / 256, 256>>>(nz4);

    // 2) 8-lane-group deposit: one particle per thread, one RED instr/particle
    int threads = 256;
    int blocks = (n_particles + threads - 1) / threads;
    cic_deposit_kernel<<<blocks, threads>>>(positions, weights, n_particles);

    // 3) depermute into d_out (fully overwrites it)
    int n4 = out_size / 4;
    depermute_kernel<<<(n4 + 255) / 256, 256>>>((float4*)grid, n4);
}